// round 17
// baseline (speedup 1.0000x reference)
#include <cuda_runtime.h>
#include <cuda_fp16.h>
#include <stdint.h>
#include <math.h>

#define NB 1024

__device__ __align__(16) __half g_Wh[131072];   // W1|W2|W3 row-major [FIN][FOUT] fp16
__device__ unsigned g_mask[NB * 512];
__device__ float    g_dinv[NB * 128];
__device__ __align__(16) __half g_Ha[(size_t)NB * 128 * 256];
__device__ __align__(16) __half g_Hb[(size_t)NB * 128 * 256];

// ---- per-CTA smem layout (bytes) ----
#define OFF_DINV 0
#define OFF_MSK  512         // mask fp16 [128][136]
#define OFF_T    35328       // T fp16 [128][136]
#define OFF_A    70144       // 2 x A-block [128][40] halves
#define ABUF     10240
#define OFF_W    90624       // 2 x W-block [32][136] halves
#define WBUF     8704
#define SMEM_SZ  108032
#define ST 136
#define SA 40
#define SWL 136

__device__ __forceinline__ uint32_t s2u(const void* p) {
    uint32_t a;
    asm("{ .reg .u64 t; cvta.to.shared.u64 t, %1; cvt.u32.u64 %0, t; }" : "=r"(a) : "l"(p));
    return a;
}
__device__ __forceinline__ unsigned pk(float a, float b) {
    __half2 h = __floats2half2_rn(a, b);
    return *(unsigned*)&h;
}
__device__ __forceinline__ float elu_neg(float v) { return __expf(v) - 1.0f; }
__device__ __forceinline__ void ldsm4(uint32_t* r, uint32_t a) {
    asm volatile("ldmatrix.sync.aligned.m8n8.x4.shared.b16 {%0,%1,%2,%3}, [%4];"
                 : "=r"(r[0]), "=r"(r[1]), "=r"(r[2]), "=r"(r[3]) : "r"(a));
}
__device__ __forceinline__ void ldsm4t(uint32_t* r, uint32_t a) {
    asm volatile("ldmatrix.sync.aligned.m8n8.x4.trans.shared.b16 {%0,%1,%2,%3}, [%4];"
                 : "=r"(r[0]), "=r"(r[1]), "=r"(r[2]), "=r"(r[3]) : "r"(a));
}
__device__ __forceinline__ void mma16816(float* c, const uint32_t* a, uint32_t b0, uint32_t b1) {
    asm volatile(
        "mma.sync.aligned.m16n8k16.row.col.f32.f16.f16.f32 "
        "{%0,%1,%2,%3}, {%4,%5,%6,%7}, {%8,%9}, {%0,%1,%2,%3};"
        : "+f"(c[0]), "+f"(c[1]), "+f"(c[2]), "+f"(c[3])
        : "r"(a[0]), "r"(a[1]), "r"(a[2]), "r"(a[3]), "r"(b0), "r"(b1));
}
__device__ __forceinline__ void cp16(uint32_t s, const void* g) {
    unsigned long long ga = (unsigned long long)__cvta_generic_to_global(g);
    asm volatile("cp.async.ca.shared.global [%0], [%1], 16;" :: "r"(s), "l"(ga) : "memory");
}
#define CP_COMMIT asm volatile("cp.async.commit_group;" ::: "memory")
#define CP_WAIT0  asm volatile("cp.async.wait_group 0;" ::: "memory")
#define GRP_BAR(g) asm volatile("bar.sync %0, %1;" :: "r"((g) + 1), "r"(128) : "memory")

// ---------------- preps ----------------
__global__ __launch_bounds__(256) void prep_w(const float* __restrict__ W1,
                                              const float* __restrict__ W2,
                                              const float* __restrict__ W3) {
    int id = blockIdx.x * 256 + threadIdx.x;
    const float* W; int base, l;
    if (id < 32768)      { W = W1; base = 0;     l = id; }
    else if (id < 98304) { W = W2; base = 32768; l = id - 32768; }
    else                 { W = W3; base = 98304; l = id - 98304; }
    g_Wh[base + l] = __float2half_rn(W[l]);
}
__global__ __launch_bounds__(256) void prep_mask(const float* __restrict__ adj) {
    int b = blockIdx.x, warp = threadIdx.x >> 5, lane = threadIdx.x & 31;
    for (int r = warp; r < 128; r += 8) {
        const float* a = adj + ((size_t)b * 128 + r) * 128;
        unsigned m[4]; int deg = 0;
#pragma unroll
        for (int s = 0; s < 4; ++s) {
            unsigned w = __ballot_sync(0xffffffffu, a[lane + 32 * s] != 0.0f);
            if (s == (r >> 5)) w |= 1u << (r & 31);
            m[s] = w; deg += __popc(w);
        }
        if (lane == 0) {
            g_dinv[b * 128 + r] = rsqrtf((float)deg);
#pragma unroll
            for (int s = 0; s < 4; ++s) g_mask[(b * 128 + r) * 4 + s] = m[s];
        }
    }
}
__global__ __launch_bounds__(256) void prep_x(const float* __restrict__ x) {
    size_t id = (size_t)blockIdx.x * 256 + threadIdx.x;   // 8388608 pairs
    ((unsigned*)g_Ha)[id] = pk(x[2 * id], x[2 * id + 1]);
}

// ---------------- one layer kernel (N-split: CTA = 128 rows x 128 cols) ----------------
template <int FIN, int FOUT, bool ELU, bool LAST>
__global__ void __launch_bounds__(256, 2) gcn_layer(
    const __half* __restrict__ Hin, const float* __restrict__ bias,
    __half* __restrict__ Hout, float* __restrict__ outf, int wbase) {
    extern __shared__ char smem[];
    const uint32_t sb = s2u(smem);
    const int b = blockIdx.x, nh = blockIdx.y, tid = threadIdx.x;
    const int lane = tid & 31, wid = tid >> 5;
    const int wm = wid >> 1, wn = wid & 1;               // 4 x 2 warp grid
    constexpr int KB = FIN / 32;
    constexpr int NT16 = 4, NT8 = 8;                     // 64 cols per warp

    const __half* hin = Hin + (size_t)b * 128 * FIN;

    // stage helpers (A: [128 rows][32 k]; W: [32 k][128 own cols])
    auto stageA = [&](int kb, int buf) {
#pragma unroll
        for (int u = 0; u < 2; ++u) {
            int i = tid + u * 256;                       // 0..511
            int r = i >> 2, c8 = (i & 3) * 8;
            cp16(sb + OFF_A + buf * ABUF + (uint32_t)(r * SA + c8) * 2,
                 hin + (size_t)r * FIN + kb * 32 + c8);
        }
    };
    auto stageW = [&](int kb, int buf) {
#pragma unroll
        for (int u = 0; u < 2; ++u) {
            int i = tid + u * 256;
            int r = i >> 4, c8 = (i & 15) * 8;
            cp16(sb + OFF_W + buf * WBUF + (uint32_t)(r * SWL + c8) * 2,
                 g_Wh + (size_t)wbase + (size_t)(kb * 32 + r) * FOUT + nh * 128 + c8);
        }
    };

    stageA(0, 0); stageW(0, 0);
    CP_COMMIT;

    // dinv + fp16 mask build from bitmask words
    float* sDinv = (float*)(smem + OFF_DINV);
    if (tid < 128) sDinv[tid] = g_dinv[b * 128 + tid];
    for (int idx = tid; idx < 4096; idx += 256) {
        int i = idx >> 5, j4 = (idx & 31) * 4;
        unsigned w = g_mask[b * 512 + i * 4 + (j4 >> 5)];
        int s4 = j4 & 31;
        unsigned u0 = (((w >> s4) & 1u) ? 0x3C00u : 0u) | (((w >> (s4 + 1)) & 1u) ? 0x3C000000u : 0u);
        unsigned u1 = (((w >> (s4 + 2)) & 1u) ? 0x3C00u : 0u) | (((w >> (s4 + 3)) & 1u) ? 0x3C000000u : 0u);
        *(uint2*)(smem + OFF_MSK + (i * ST + j4) * 2) = make_uint2(u0, u1);
    }
    CP_WAIT0;
    __syncthreads();

    const uint32_t aRow  = (uint32_t)(wm * 32 + (lane & 15));
    const uint32_t aCol8 = (uint32_t)((lane >> 4) * 8);
    const uint32_t bRow  = (uint32_t)((lane & 7) + ((lane >> 3) & 1) * 8);
    const uint32_t bCol8 = (uint32_t)((lane >> 4) * 8);

    // ---- GEMM1: T = H @ W (this CTA's 128-col slice) ----
    float acc[2][NT8][4];
#pragma unroll
    for (int m = 0; m < 2; ++m)
#pragma unroll
        for (int i = 0; i < NT8; ++i)
#pragma unroll
            for (int q = 0; q < 4; ++q) acc[m][i][q] = 0.0f;

    for (int kb = 0; kb < KB; ++kb) {
        if (kb + 1 < KB) { stageA(kb + 1, (kb + 1) & 1); stageW(kb + 1, (kb + 1) & 1); }
        CP_COMMIT;
        uint32_t ab_ = sb + OFF_A + (kb & 1) * ABUF;
        uint32_t wb_ = sb + OFF_W + (kb & 1) * WBUF;
#pragma unroll
        for (int ks = 0; ks < 2; ++ks) {
            uint32_t ah[2][4];
#pragma unroll
            for (int m = 0; m < 2; ++m)
                ldsm4(ah[m], ab_ + ((aRow + 16 * m) * SA + ks * 16 + aCol8) * 2);
            uint32_t bh[NT16][4];
#pragma unroll
            for (int t = 0; t < NT16; ++t)
                ldsm4t(bh[t], wb_ + ((ks * 16 + bRow) * SWL + wn * 64 + t * 16 + bCol8) * 2);
#pragma unroll
            for (int t = 0; t < NT16; ++t)
#pragma unroll
                for (int m = 0; m < 2; ++m) {
                    mma16816(acc[m][2 * t], ah[m], bh[t][0], bh[t][1]);
                    mma16816(acc[m][2 * t + 1], ah[m], bh[t][2], bh[t][3]);
                }
        }
        CP_WAIT0;
        __syncthreads();
    }

    // ---- epilogue1: T * dinv_row -> smem T (own half-columns) ----
#pragma unroll
    for (int m = 0; m < 2; ++m) {
        int r0 = wm * 32 + m * 16 + (lane >> 2), r1 = r0 + 8;
        float d0 = sDinv[r0], d1 = sDinv[r1];
#pragma unroll
        for (int i = 0; i < NT8; ++i) {
            int col = wn * 64 + i * 8 + (lane & 3) * 2;
            *(unsigned*)(smem + OFF_T + (r0 * ST + col) * 2) =
                pk(acc[m][i][0] * d0, acc[m][i][1] * d0);
            *(unsigned*)(smem + OFF_T + (r1 * ST + col) * 2) =
                pk(acc[m][i][2] * d1, acc[m][i][3] * d1);
        }
    }
    // GEMM2's B-reads of half wn depend only on the 4 warps with same wn
    GRP_BAR(wn);

    // ---- GEMM2: out = Mask @ T ----
    float ac2[2][NT8][4];
#pragma unroll
    for (int m = 0; m < 2; ++m)
#pragma unroll
        for (int i = 0; i < NT8; ++i)
#pragma unroll
            for (int q = 0; q < 4; ++q) ac2[m][i][q] = 0.0f;

#pragma unroll
    for (int k = 0; k < 8; ++k) {
        uint32_t am[2][4];
#pragma unroll
        for (int m = 0; m < 2; ++m)
            ldsm4(am[m], sb + OFF_MSK + ((aRow + 16 * m) * ST + k * 16 + aCol8) * 2);
        uint32_t th[NT16][4];
#pragma unroll
        for (int t = 0; t < NT16; ++t)
            ldsm4t(th[t], sb + OFF_T + ((k * 16 + bRow) * ST + wn * 64 + t * 16 + bCol8) * 2);
#pragma unroll
        for (int t = 0; t < NT16; ++t)
#pragma unroll
            for (int m = 0; m < 2; ++m) {
                mma16816(ac2[m][2 * t], am[m], th[t][0], th[t][1]);
                mma16816(ac2[m][2 * t + 1], am[m], th[t][2], th[t][3]);
            }
    }

    // ---- epilogue2: *dinv_i + bias, ELU -> global (no barrier needed) ----
#pragma unroll
    for (int m = 0; m < 2; ++m) {
        int r0 = wm * 32 + m * 16 + (lane >> 2), r1 = r0 + 8;
        float d0 = sDinv[r0], d1 = sDinv[r1];
#pragma unroll
        for (int i = 0; i < NT8; ++i) {
            int col = wn * 64 + i * 8 + (lane & 3) * 2;
            float2 bv = __ldg((const float2*)(bias + nh * 128 + col));
            float v00 = fmaf(ac2[m][i][0], d0, bv.x), v01 = fmaf(ac2[m][i][1], d0, bv.y);
            float v10 = fmaf(ac2[m][i][2], d1, bv.x), v11 = fmaf(ac2[m][i][3], d1, bv.y);
            if (ELU) {
                v00 = v00 > 0.f ? v00 : elu_neg(v00);
                v01 = v01 > 0.f ? v01 : elu_neg(v01);
                v10 = v10 > 0.f ? v10 : elu_neg(v10);
                v11 = v11 > 0.f ? v11 : elu_neg(v11);
            }
            if (LAST) {
                *(float2*)(outf + ((size_t)b * 128 + r0) * 128 + col) = make_float2(v00, v01);
                *(float2*)(outf + ((size_t)b * 128 + r1) * 128 + col) = make_float2(v10, v11);
            } else {
                *(unsigned*)(Hout + ((size_t)b * 128 + r0) * FOUT + nh * 128 + col) = pk(v00, v01);
                *(unsigned*)(Hout + ((size_t)b * 128 + r1) * FOUT + nh * 128 + col) = pk(v10, v11);
            }
        }
    }
}

// ---------------------------------------------------------------------------
extern "C" void kernel_launch(void* const* d_in, const int* in_sizes, int n_in,
                              void* d_out, int out_size) {
    const float* x   = (const float*)d_in[0];
    const float* adj = (const float*)d_in[1];
    const float* W1  = (const float*)d_in[2];
    const float* b1  = (const float*)d_in[3];
    const float* W2  = (const float*)d_in[4];
    const float* b2  = (const float*)d_in[5];
    const float* W3  = (const float*)d_in[6];
    const float* b3  = (const float*)d_in[7];
    float* out = (float*)d_out;

    void *pa = nullptr, *pb = nullptr;
    cudaGetSymbolAddress(&pa, g_Ha);
    cudaGetSymbolAddress(&pb, g_Hb);
    __half* Ha = (__half*)pa;
    __half* Hb = (__half*)pb;

    cudaFuncSetAttribute(gcn_layer<128, 256, true,  false>, cudaFuncAttributeMaxDynamicSharedMemorySize, SMEM_SZ);
    cudaFuncSetAttribute(gcn_layer<256, 256, true,  false>, cudaFuncAttributeMaxDynamicSharedMemorySize, SMEM_SZ);
    cudaFuncSetAttribute(gcn_layer<256, 128, false, true >, cudaFuncAttributeMaxDynamicSharedMemorySize, SMEM_SZ);

    prep_w<<<512, 256>>>(W1, W2, W3);
    prep_mask<<<NB, 256>>>(adj);
    prep_x<<<32768, 256>>>(x);

    dim3 g2(NB, 2), g1l(NB, 1);
    gcn_layer<128, 256, true,  false><<<g2,  256, SMEM_SZ>>>(Ha, b1, Hb, nullptr, 0);
    gcn_layer<256, 256, true,  false><<<g2,  256, SMEM_SZ>>>(Hb, b2, Ha, nullptr, 32768);
    gcn_layer<256, 128, false, true ><<<g1l, 256, SMEM_SZ>>>(Ha, b3, nullptr, out, 98304);
}